// round 3
// baseline (speedup 1.0000x reference)
#include <cuda_runtime.h>
#include <math.h>

// Problem constants
#define BB   8
#define TT   4096
#define DD   1024
#define NTOK (BB*TT)          // 32768
#define K2   (2*DD)           // 2048

// ---------------- scratch (static device globals: allowed) ----------------
__device__ float g_spart[8 * NTOK];          // per-eblock partial scores, 1 MB
__device__ float g_e[NTOK];                  // exp(s - m) per token
__device__ float g_ctx[(size_t)NTOK * DD];   // 128 MB ctx buffer

// ---------------- f32x2 helpers (sm_103a packed fp32 pipe) ----------------
using u64 = unsigned long long;

__device__ __forceinline__ u64 pack_dup(float a) {
    u64 r; unsigned int ai = __float_as_uint(a);
    asm("mov.b64 %0, {%1, %1};" : "=l"(r) : "r"(ai));
    return r;
}
__device__ __forceinline__ void fma2(u64& c, u64 a, u64 b) {
    asm("fma.rn.f32x2 %0, %1, %2, %0;" : "+l"(c) : "l"(a), "l"(b));
}
__device__ __forceinline__ void unpack2(u64 v, float& lo, float& hi) {
    unsigned int l, h;
    asm("mov.b64 {%0, %1}, %2;" : "=r"(l), "=r"(h) : "l"(v));
    lo = __uint_as_float(l); hi = __uint_as_float(h);
}

// =====================================================================
// Kernel 1: scores.  s_part[eb][n] = sum_{e in eblock} tanh(X·W1^T + b1)*w2
// 128x128x8 tile, 256 threads, 8x8 microtile (2x2 quadrants of 4x4),
// fma.rn.f32x2 inner loop.
// =====================================================================
#define KT 8
#define SMEM_FLOATS ((2*KT*132) > (128*17) ? (2*KT*132) : (128*17))

__global__ __launch_bounds__(256, 2)
void gemm_score(const float* __restrict__ X, const float* __restrict__ W1,
                const float* __restrict__ b1, const float* __restrict__ w2)
{
    __shared__ __align__(16) float smem[SMEM_FLOATS];
    float (*As)[132] = reinterpret_cast<float(*)[132]>(smem);
    float (*Bs)[132] = reinterpret_cast<float(*)[132]>(smem + KT*132);

    const int n0 = blockIdx.x * 128;
    const int e0 = blockIdx.y * 128;
    const int tid = threadIdx.x;
    const int tx = tid & 15, ty = tid >> 4;
    const int lrow = tid >> 1, lk4 = (tid & 1) * 4;

    const float* Aptr = X  + (size_t)(n0 + lrow) * DD + lk4;
    const float* Bptr = W1 + (size_t)(e0 + lrow) * DD + lk4;

    u64 c2[8][4];
#pragma unroll
    for (int i = 0; i < 8; i++)
#pragma unroll
        for (int j = 0; j < 4; j++) c2[i][j] = 0ull;

    float4 aReg = *(const float4*)Aptr;
    float4 bReg = *(const float4*)Bptr;

    const int KTILES = DD / KT;   // 128
    for (int kt = 0; kt < KTILES; ++kt) {
        __syncthreads();
        As[lk4+0][lrow] = aReg.x; As[lk4+1][lrow] = aReg.y;
        As[lk4+2][lrow] = aReg.z; As[lk4+3][lrow] = aReg.w;
        Bs[lk4+0][lrow] = bReg.x; Bs[lk4+1][lrow] = bReg.y;
        Bs[lk4+2][lrow] = bReg.z; Bs[lk4+3][lrow] = bReg.w;
        __syncthreads();
        if (kt + 1 < KTILES) {
            aReg = *(const float4*)(Aptr + (size_t)(kt+1) * KT);
            bReg = *(const float4*)(Bptr + (size_t)(kt+1) * KT);
        }
#pragma unroll
        for (int k = 0; k < KT; k++) {
            float4 a0 = *(const float4*)&As[k][ty*4];
            float4 a1 = *(const float4*)&As[k][64 + ty*4];
            ulonglong2 b01 = *(const ulonglong2*)&Bs[k][tx*4];
            ulonglong2 b23 = *(const ulonglong2*)&Bs[k][64 + tx*4];
            float av[8] = {a0.x,a0.y,a0.z,a0.w,a1.x,a1.y,a1.z,a1.w};
#pragma unroll
            for (int i = 0; i < 8; i++) {
                u64 ad = pack_dup(av[i]);
                fma2(c2[i][0], ad, b01.x);
                fma2(c2[i][1], ad, b01.y);
                fma2(c2[i][2], ad, b23.x);
                fma2(c2[i][3], ad, b23.y);
            }
        }
    }

    // epilogue: tanh(c + b1[e]) * w2[e], reduced over this block's 128 e-cols
    float p[8] = {0,0,0,0,0,0,0,0};
#pragma unroll
    for (int jp = 0; jp < 4; jp++) {
        int col0 = e0 + ((jp < 2) ? (tx*4 + jp*2) : (64 + tx*4 + (jp-2)*2));
        float w2a = w2[col0], w2b = w2[col0+1];
        float b1a = b1[col0], b1b = b1[col0+1];
#pragma unroll
        for (int i = 0; i < 8; i++) {
            float lo, hi; unpack2(c2[i][jp], lo, hi);
            p[i] += tanhf(lo + b1a) * w2a + tanhf(hi + b1b) * w2b;
        }
    }
    __syncthreads();   // reuse smem as reduction buffer
    float* red = smem; // [128][17]
#pragma unroll
    for (int i = 0; i < 8; i++) {
        int r = (i < 4) ? (ty*4 + i) : (64 + ty*4 + (i-4));
        red[r*17 + tx] = p[i];
    }
    __syncthreads();
    if (tid < 128) {
        float s = 0.f;
#pragma unroll
        for (int j = 0; j < 16; j++) s += red[tid*17 + j];
        g_spart[(size_t)blockIdx.y * NTOK + n0 + tid] = s;
    }
}

// =====================================================================
// Kernel 2: per-batch max + e = exp(s + b2 - m)
// =====================================================================
__global__ void softmax_prep(const float* __restrict__ b2)
{
    const int b = blockIdx.x, tid = threadIdx.x;   // 256 threads
    float vloc[16];
    float mx = -INFINITY;
    const float b2v = b2[0];
#pragma unroll
    for (int i = 0; i < 16; i++) {
        int t = tid + i * 256;
        float s = 0.f;
#pragma unroll
        for (int eb = 0; eb < 8; eb++) s += g_spart[(size_t)eb * NTOK + b * TT + t];
        s += b2v;
        vloc[i] = s;
        mx = fmaxf(mx, s);
    }
    __shared__ float sm[256];
    sm[tid] = mx; __syncthreads();
    for (int off = 128; off > 0; off >>= 1) {
        if (tid < off) sm[tid] = fmaxf(sm[tid], sm[tid + off]);
        __syncthreads();
    }
    float m = sm[0];
#pragma unroll
    for (int i = 0; i < 16; i++) {
        int t = tid + i * 256;
        g_e[b * TT + t] = expf(vloc[i] - m);
    }
}

// =====================================================================
// Kernel 3: causal prefix scan.  ctx[b,t,d] = cumsum(e*x)/cumsum(e)
// grid (D/128, B), 128 threads; thread owns one d, loops T sequentially.
// =====================================================================
__global__ void scan_kernel(const float* __restrict__ X)
{
    const int b = blockIdx.y;
    const int d = blockIdx.x * 128 + threadIdx.x;
    const float* xb = X     + (size_t)b * TT * DD + d;
    float*       cb = g_ctx + (size_t)b * TT * DD + d;

    __shared__ float es[128];
    float num = 0.f, den = 0.f;

    for (int tc = 0; tc < TT; tc += 128) {
        __syncthreads();
        es[threadIdx.x] = g_e[b * TT + tc + threadIdx.x];
        __syncthreads();
#pragma unroll 8
        for (int tt = 0; tt < 128; ++tt) {
            float ev = es[tt];
            den += ev;
            num = fmaf(ev, xb[(size_t)(tc + tt) * DD], num);
            float r;
            asm("rcp.approx.f32 %0, %1;" : "=f"(r) : "f"(den));
            cb[(size_t)(tc + tt) * DD] = num * r;
        }
    }
}

// =====================================================================
// Kernel 4: out = tanh([ctx, x] · Wc^T + bc), K split ctx(0:1024)/x(1024:2048)
// =====================================================================
__global__ __launch_bounds__(256, 2)
void gemm_out(const float* __restrict__ X, const float* __restrict__ Wc,
              const float* __restrict__ bc, float* __restrict__ out)
{
    __shared__ __align__(16) float smem[2*KT*132];
    float (*As)[132] = reinterpret_cast<float(*)[132]>(smem);
    float (*Bs)[132] = reinterpret_cast<float(*)[132]>(smem + KT*132);

    const int n0 = blockIdx.x * 128;
    const int d0 = blockIdx.y * 128;
    const int tid = threadIdx.x;
    const int tx = tid & 15, ty = tid >> 4;
    const int lrow = tid >> 1, lk4 = (tid & 1) * 4;

    const float* Actx = g_ctx + (size_t)(n0 + lrow) * DD + lk4;
    const float* Ax   = X     + (size_t)(n0 + lrow) * DD + lk4;
    const float* Bptr = Wc    + (size_t)(d0 + lrow) * K2 + lk4;

    u64 c2[8][4];
#pragma unroll
    for (int i = 0; i < 8; i++)
#pragma unroll
        for (int j = 0; j < 4; j++) c2[i][j] = 0ull;

    const int KTILES = K2 / KT;  // 256
    float4 aReg, bReg;
    {
        aReg = *(const float4*)Actx;         // kt=0 always in ctx half
        bReg = *(const float4*)Bptr;
    }
    for (int kt = 0; kt < KTILES; ++kt) {
        __syncthreads();
        As[lk4+0][lrow] = aReg.x; As[lk4+1][lrow] = aReg.y;
        As[lk4+2][lrow] = aReg.z; As[lk4+3][lrow] = aReg.w;
        Bs[lk4+0][lrow] = bReg.x; Bs[lk4+1][lrow] = bReg.y;
        Bs[lk4+2][lrow] = bReg.z; Bs[lk4+3][lrow] = bReg.w;
        __syncthreads();
        if (kt + 1 < KTILES) {
            int kk = (kt + 1) * KT;
            const float* an = (kk < DD) ? (Actx + kk) : (Ax + (kk - DD));
            aReg = *(const float4*)an;
            bReg = *(const float4*)(Bptr + (size_t)(kt+1) * KT);
        }
#pragma unroll
        for (int k = 0; k < KT; k++) {
            float4 a0 = *(const float4*)&As[k][ty*4];
            float4 a1 = *(const float4*)&As[k][64 + ty*4];
            ulonglong2 b01 = *(const ulonglong2*)&Bs[k][tx*4];
            ulonglong2 b23 = *(const ulonglong2*)&Bs[k][64 + tx*4];
            float av[8] = {a0.x,a0.y,a0.z,a0.w,a1.x,a1.y,a1.z,a1.w};
#pragma unroll
            for (int i = 0; i < 8; i++) {
                u64 ad = pack_dup(av[i]);
                fma2(c2[i][0], ad, b01.x);
                fma2(c2[i][1], ad, b01.y);
                fma2(c2[i][2], ad, b23.x);
                fma2(c2[i][3], ad, b23.y);
            }
        }
    }

    // epilogue: tanh(c + bc), vectorized stores (fully coalesced across tx)
    float4 bcA = *(const float4*)&bc[d0 + tx*4];
    float4 bcB = *(const float4*)&bc[d0 + 64 + tx*4];
#pragma unroll
    for (int i = 0; i < 8; i++) {
        int r = (i < 4) ? (ty*4 + i) : (64 + ty*4 + (i-4));
        size_t ro = (size_t)(n0 + r) * DD;
        float v0, v1, v2, v3;
        unpack2(c2[i][0], v0, v1);
        unpack2(c2[i][1], v2, v3);
        float4 o;
        o.x = tanhf(v0 + bcA.x); o.y = tanhf(v1 + bcA.y);
        o.z = tanhf(v2 + bcA.z); o.w = tanhf(v3 + bcA.w);
        *(float4*)&out[ro + d0 + tx*4] = o;
        unpack2(c2[i][2], v0, v1);
        unpack2(c2[i][3], v2, v3);
        o.x = tanhf(v0 + bcB.x); o.y = tanhf(v1 + bcB.y);
        o.z = tanhf(v2 + bcB.z); o.w = tanhf(v3 + bcB.w);
        *(float4*)&out[ro + d0 + 64 + tx*4] = o;
    }
}

// =====================================================================
extern "C" void kernel_launch(void* const* d_in, const int* in_sizes, int n_in,
                              void* d_out, int out_size)
{
    const float* x  = (const float*)d_in[0];
    const float* W1 = (const float*)d_in[1];
    const float* b1 = (const float*)d_in[2];
    const float* w2 = (const float*)d_in[3];
    const float* b2 = (const float*)d_in[4];
    const float* Wc = (const float*)d_in[5];
    const float* bc = (const float*)d_in[6];
    float* out = (float*)d_out;

    dim3 g1(NTOK / 128, DD / 128);      // 256 x 8
    gemm_score<<<g1, 256>>>(x, W1, b1, w2);

    softmax_prep<<<BB, 256>>>(b2);

    dim3 g3(DD / 128, BB);              // 8 x 8
    scan_kernel<<<g3, 128>>>(x);

    dim3 g4(NTOK / 128, DD / 128);      // 256 x 8
    gemm_out<<<g4, 256>>>(x, Wc, bc, out);
}

// round 4
// speedup vs baseline: 1.0004x; 1.0004x over previous
#include <cuda_runtime.h>
#include <math.h>

// Problem constants
#define BB   8
#define TT   4096
#define DD   1024
#define NTOK (BB*TT)          // 32768
#define K2   (2*DD)           // 2048

// ---------------- scratch (static device globals: allowed) ----------------
__device__ float g_spart[8 * NTOK];          // per-eblock partial scores, 1 MB
__device__ float g_e[NTOK];                  // exp(s - m) per token
__device__ float g_ctx[(size_t)NTOK * DD];   // 128 MB ctx buffer

// ---------------- f32x2 helpers (sm_103a packed fp32 pipe) ----------------
using u64 = unsigned long long;

__device__ __forceinline__ u64 pack_dup(float a) {
    u64 r; unsigned int ai = __float_as_uint(a);
    asm("mov.b64 %0, {%1, %1};" : "=l"(r) : "r"(ai));
    return r;
}
__device__ __forceinline__ void fma2(u64& c, u64 a, u64 b) {
    asm("fma.rn.f32x2 %0, %1, %2, %0;" : "+l"(c) : "l"(a), "l"(b));
}
__device__ __forceinline__ void unpack2(u64 v, float& lo, float& hi) {
    unsigned int l, h;
    asm("mov.b64 {%0, %1}, %2;" : "=r"(l), "=r"(h) : "l"(v));
    lo = __uint_as_float(l); hi = __uint_as_float(h);
}

// =====================================================================
// Kernel 1: scores.  s_part[eb][n] = sum_{e in eblock} tanh(X·W1^T + b1)*w2
// 128x128x8 tile, 256 threads, 8x8 microtile (2x2 quadrants of 4x4),
// fma.rn.f32x2 inner loop.
// =====================================================================
#define KT 8
#define SMEM_FLOATS ((2*KT*132) > (128*17) ? (2*KT*132) : (128*17))

__global__ __launch_bounds__(256, 2)
void gemm_score(const float* __restrict__ X, const float* __restrict__ W1,
                const float* __restrict__ b1, const float* __restrict__ w2)
{
    __shared__ __align__(16) float smem[SMEM_FLOATS];
    float (*As)[132] = reinterpret_cast<float(*)[132]>(smem);
    float (*Bs)[132] = reinterpret_cast<float(*)[132]>(smem + KT*132);

    const int n0 = blockIdx.x * 128;
    const int e0 = blockIdx.y * 128;
    const int tid = threadIdx.x;
    const int tx = tid & 15, ty = tid >> 4;
    const int lrow = tid >> 1, lk4 = (tid & 1) * 4;

    const float* Aptr = X  + (size_t)(n0 + lrow) * DD + lk4;
    const float* Bptr = W1 + (size_t)(e0 + lrow) * DD + lk4;

    u64 c2[8][4];
#pragma unroll
    for (int i = 0; i < 8; i++)
#pragma unroll
        for (int j = 0; j < 4; j++) c2[i][j] = 0ull;

    float4 aReg = *(const float4*)Aptr;
    float4 bReg = *(const float4*)Bptr;

    const int KTILES = DD / KT;   // 128
    for (int kt = 0; kt < KTILES; ++kt) {
        __syncthreads();
        As[lk4+0][lrow] = aReg.x; As[lk4+1][lrow] = aReg.y;
        As[lk4+2][lrow] = aReg.z; As[lk4+3][lrow] = aReg.w;
        Bs[lk4+0][lrow] = bReg.x; Bs[lk4+1][lrow] = bReg.y;
        Bs[lk4+2][lrow] = bReg.z; Bs[lk4+3][lrow] = bReg.w;
        __syncthreads();
        if (kt + 1 < KTILES) {
            aReg = *(const float4*)(Aptr + (size_t)(kt+1) * KT);
            bReg = *(const float4*)(Bptr + (size_t)(kt+1) * KT);
        }
#pragma unroll
        for (int k = 0; k < KT; k++) {
            float4 a0 = *(const float4*)&As[k][ty*4];
            float4 a1 = *(const float4*)&As[k][64 + ty*4];
            ulonglong2 b01 = *(const ulonglong2*)&Bs[k][tx*4];
            ulonglong2 b23 = *(const ulonglong2*)&Bs[k][64 + tx*4];
            float av[8] = {a0.x,a0.y,a0.z,a0.w,a1.x,a1.y,a1.z,a1.w};
#pragma unroll
            for (int i = 0; i < 8; i++) {
                u64 ad = pack_dup(av[i]);
                fma2(c2[i][0], ad, b01.x);
                fma2(c2[i][1], ad, b01.y);
                fma2(c2[i][2], ad, b23.x);
                fma2(c2[i][3], ad, b23.y);
            }
        }
    }

    // epilogue: tanh(c + b1[e]) * w2[e], reduced over this block's 128 e-cols
    float p[8] = {0,0,0,0,0,0,0,0};
#pragma unroll
    for (int jp = 0; jp < 4; jp++) {
        int col0 = e0 + ((jp < 2) ? (tx*4 + jp*2) : (64 + tx*4 + (jp-2)*2));
        float w2a = w2[col0], w2b = w2[col0+1];
        float b1a = b1[col0], b1b = b1[col0+1];
#pragma unroll
        for (int i = 0; i < 8; i++) {
            float lo, hi; unpack2(c2[i][jp], lo, hi);
            p[i] += tanhf(lo + b1a) * w2a + tanhf(hi + b1b) * w2b;
        }
    }
    __syncthreads();   // reuse smem as reduction buffer
    float* red = smem; // [128][17]
#pragma unroll
    for (int i = 0; i < 8; i++) {
        int r = (i < 4) ? (ty*4 + i) : (64 + ty*4 + (i-4));
        red[r*17 + tx] = p[i];
    }
    __syncthreads();
    if (tid < 128) {
        float s = 0.f;
#pragma unroll
        for (int j = 0; j < 16; j++) s += red[tid*17 + j];
        g_spart[(size_t)blockIdx.y * NTOK + n0 + tid] = s;
    }
}

// =====================================================================
// Kernel 2: per-batch max + e = exp(s + b2 - m)
// =====================================================================
__global__ void softmax_prep(const float* __restrict__ b2)
{
    const int b = blockIdx.x, tid = threadIdx.x;   // 256 threads
    float vloc[16];
    float mx = -INFINITY;
    const float b2v = b2[0];
#pragma unroll
    for (int i = 0; i < 16; i++) {
        int t = tid + i * 256;
        float s = 0.f;
#pragma unroll
        for (int eb = 0; eb < 8; eb++) s += g_spart[(size_t)eb * NTOK + b * TT + t];
        s += b2v;
        vloc[i] = s;
        mx = fmaxf(mx, s);
    }
    __shared__ float sm[256];
    sm[tid] = mx; __syncthreads();
    for (int off = 128; off > 0; off >>= 1) {
        if (tid < off) sm[tid] = fmaxf(sm[tid], sm[tid + off]);
        __syncthreads();
    }
    float m = sm[0];
#pragma unroll
    for (int i = 0; i < 16; i++) {
        int t = tid + i * 256;
        g_e[b * TT + t] = expf(vloc[i] - m);
    }
}

// =====================================================================
// Kernel 3: causal prefix scan.  ctx[b,t,d] = cumsum(e*x)/cumsum(e)
// grid (D/128, B), 128 threads; thread owns one d, loops T sequentially.
// =====================================================================
__global__ void scan_kernel(const float* __restrict__ X)
{
    const int b = blockIdx.y;
    const int d = blockIdx.x * 128 + threadIdx.x;
    const float* xb = X     + (size_t)b * TT * DD + d;
    float*       cb = g_ctx + (size_t)b * TT * DD + d;

    __shared__ float es[128];
    float num = 0.f, den = 0.f;

    for (int tc = 0; tc < TT; tc += 128) {
        __syncthreads();
        es[threadIdx.x] = g_e[b * TT + tc + threadIdx.x];
        __syncthreads();
#pragma unroll 8
        for (int tt = 0; tt < 128; ++tt) {
            float ev = es[tt];
            den += ev;
            num = fmaf(ev, xb[(size_t)(tc + tt) * DD], num);
            float r;
            asm("rcp.approx.f32 %0, %1;" : "=f"(r) : "f"(den));
            cb[(size_t)(tc + tt) * DD] = num * r;
        }
    }
}

// =====================================================================
// Kernel 4: out = tanh([ctx, x] · Wc^T + bc), K split ctx(0:1024)/x(1024:2048)
// =====================================================================
__global__ __launch_bounds__(256, 2)
void gemm_out(const float* __restrict__ X, const float* __restrict__ Wc,
              const float* __restrict__ bc, float* __restrict__ out)
{
    __shared__ __align__(16) float smem[2*KT*132];
    float (*As)[132] = reinterpret_cast<float(*)[132]>(smem);
    float (*Bs)[132] = reinterpret_cast<float(*)[132]>(smem + KT*132);

    const int n0 = blockIdx.x * 128;
    const int d0 = blockIdx.y * 128;
    const int tid = threadIdx.x;
    const int tx = tid & 15, ty = tid >> 4;
    const int lrow = tid >> 1, lk4 = (tid & 1) * 4;

    const float* Actx = g_ctx + (size_t)(n0 + lrow) * DD + lk4;
    const float* Ax   = X     + (size_t)(n0 + lrow) * DD + lk4;
    const float* Bptr = Wc    + (size_t)(d0 + lrow) * K2 + lk4;

    u64 c2[8][4];
#pragma unroll
    for (int i = 0; i < 8; i++)
#pragma unroll
        for (int j = 0; j < 4; j++) c2[i][j] = 0ull;

    const int KTILES = K2 / KT;  // 256
    float4 aReg, bReg;
    {
        aReg = *(const float4*)Actx;         // kt=0 always in ctx half
        bReg = *(const float4*)Bptr;
    }
    for (int kt = 0; kt < KTILES; ++kt) {
        __syncthreads();
        As[lk4+0][lrow] = aReg.x; As[lk4+1][lrow] = aReg.y;
        As[lk4+2][lrow] = aReg.z; As[lk4+3][lrow] = aReg.w;
        Bs[lk4+0][lrow] = bReg.x; Bs[lk4+1][lrow] = bReg.y;
        Bs[lk4+2][lrow] = bReg.z; Bs[lk4+3][lrow] = bReg.w;
        __syncthreads();
        if (kt + 1 < KTILES) {
            int kk = (kt + 1) * KT;
            const float* an = (kk < DD) ? (Actx + kk) : (Ax + (kk - DD));
            aReg = *(const float4*)an;
            bReg = *(const float4*)(Bptr + (size_t)(kt+1) * KT);
        }
#pragma unroll
        for (int k = 0; k < KT; k++) {
            float4 a0 = *(const float4*)&As[k][ty*4];
            float4 a1 = *(const float4*)&As[k][64 + ty*4];
            ulonglong2 b01 = *(const ulonglong2*)&Bs[k][tx*4];
            ulonglong2 b23 = *(const ulonglong2*)&Bs[k][64 + tx*4];
            float av[8] = {a0.x,a0.y,a0.z,a0.w,a1.x,a1.y,a1.z,a1.w};
#pragma unroll
            for (int i = 0; i < 8; i++) {
                u64 ad = pack_dup(av[i]);
                fma2(c2[i][0], ad, b01.x);
                fma2(c2[i][1], ad, b01.y);
                fma2(c2[i][2], ad, b23.x);
                fma2(c2[i][3], ad, b23.y);
            }
        }
    }

    // epilogue: tanh(c + bc), vectorized stores (fully coalesced across tx)
    float4 bcA = *(const float4*)&bc[d0 + tx*4];
    float4 bcB = *(const float4*)&bc[d0 + 64 + tx*4];
#pragma unroll
    for (int i = 0; i < 8; i++) {
        int r = (i < 4) ? (ty*4 + i) : (64 + ty*4 + (i-4));
        size_t ro = (size_t)(n0 + r) * DD;
        float v0, v1, v2, v3;
        unpack2(c2[i][0], v0, v1);
        unpack2(c2[i][1], v2, v3);
        float4 o;
        o.x = tanhf(v0 + bcA.x); o.y = tanhf(v1 + bcA.y);
        o.z = tanhf(v2 + bcA.z); o.w = tanhf(v3 + bcA.w);
        *(float4*)&out[ro + d0 + tx*4] = o;
        unpack2(c2[i][2], v0, v1);
        unpack2(c2[i][3], v2, v3);
        o.x = tanhf(v0 + bcB.x); o.y = tanhf(v1 + bcB.y);
        o.z = tanhf(v2 + bcB.z); o.w = tanhf(v3 + bcB.w);
        *(float4*)&out[ro + d0 + 64 + tx*4] = o;
    }
}

// =====================================================================
extern "C" void kernel_launch(void* const* d_in, const int* in_sizes, int n_in,
                              void* d_out, int out_size)
{
    const float* x  = (const float*)d_in[0];
    const float* W1 = (const float*)d_in[1];
    const float* b1 = (const float*)d_in[2];
    const float* w2 = (const float*)d_in[3];
    const float* b2 = (const float*)d_in[4];
    const float* Wc = (const float*)d_in[5];
    const float* bc = (const float*)d_in[6];
    float* out = (float*)d_out;

    dim3 g1(NTOK / 128, DD / 128);      // 256 x 8
    gemm_score<<<g1, 256>>>(x, W1, b1, w2);

    softmax_prep<<<BB, 256>>>(b2);

    dim3 g3(DD / 128, BB);              // 8 x 8
    scan_kernel<<<g3, 128>>>(x);

    dim3 g4(NTOK / 128, DD / 128);      // 256 x 8
    gemm_out<<<g4, 256>>>(x, Wc, bc, out);
}

// round 6
// speedup vs baseline: 1.8406x; 1.8399x over previous
#include <cuda_runtime.h>
#include <cuda_bf16.h>
#include <math.h>

// Problem constants
#define BB   8
#define TT   4096
#define DD   1024
#define NTOK (BB*TT)          // 32768
#define K2   (2*DD)           // 2048

using u32 = unsigned int;
using u64 = unsigned long long;

// ---------------- scratch (static device globals: allowed) ----------------
__device__ float g_spart[8 * NTOK];
__device__ float g_e[NTOK];
__device__ __nv_bfloat16 g_Xh[(size_t)NTOK * DD];
__device__ __nv_bfloat16 g_Xl[(size_t)NTOK * DD];
__device__ __nv_bfloat16 g_Ch[(size_t)NTOK * DD];
__device__ __nv_bfloat16 g_Cl[(size_t)NTOK * DD];
__device__ __nv_bfloat16 g_W1h[(size_t)DD * DD];
__device__ __nv_bfloat16 g_W1l[(size_t)DD * DD];
__device__ __nv_bfloat16 g_Wch[(size_t)DD * K2];
__device__ __nv_bfloat16 g_Wcl[(size_t)DD * K2];

// ---------------- helpers ----------------
__device__ __forceinline__ u32 smem_u32(const void* p) {
    u32 a;
    asm("{ .reg .u64 t; cvta.to.shared.u64 t, %1; cvt.u32.u64 %0, t; }" : "=r"(a) : "l"(p));
    return a;
}
__device__ __forceinline__ void cp16(u32 dst, const void* src) {
    asm volatile("cp.async.cg.shared.global [%0], [%1], 16;" :: "r"(dst), "l"(src));
}
#define CP_COMMIT() asm volatile("cp.async.commit_group;" ::: "memory")
#define CP_WAIT1()  asm volatile("cp.async.wait_group 1;" ::: "memory")
#define CP_WAIT0()  asm volatile("cp.async.wait_group 0;" ::: "memory")

__device__ __forceinline__ void ldsm4(u32* r, u32 addr) {
    asm volatile("ldmatrix.sync.aligned.m8n8.x4.shared.b16 {%0,%1,%2,%3}, [%4];"
                 : "=r"(r[0]), "=r"(r[1]), "=r"(r[2]), "=r"(r[3]) : "r"(addr));
}
__device__ __forceinline__ void hmma(float* c, const u32* a, u32 b0, u32 b1) {
    asm volatile("mma.sync.aligned.m16n8k16.row.col.f32.bf16.bf16.f32 "
                 "{%0,%1,%2,%3}, {%4,%5,%6,%7}, {%8,%9}, {%0,%1,%2,%3};"
                 : "+f"(c[0]), "+f"(c[1]), "+f"(c[2]), "+f"(c[3])
                 : "r"(a[0]), "r"(a[1]), "r"(a[2]), "r"(a[3]), "r"(b0), "r"(b1));
}
// accurate fast tanh: 1 - 2/(1+e^{2x})   (2 MUFU + ~4 FLOP, err ~3e-7)
__device__ __forceinline__ float tanh_acc(float x) {
    float e, r;
    asm("ex2.approx.f32 %0, %1;" : "=f"(e) : "f"(x * 2.885390081777927f)); // 2*log2(e)
    asm("rcp.approx.f32 %0, %1;" : "=f"(r) : "f"(e + 1.0f));
    return fmaf(-2.0f, r, 1.0f);
}

// smem geometry: 2 stages x (Ahi,Alo,Bhi,Blo), each tile 128 rows x 64 bf16 = 16KB
#define TILE_B   16384
#define STAGE_B  (4*TILE_B)          // 64 KB
#define DYN_B    (2*STAGE_B + 1024)

// load one 128x64-bf16 tile into SW128-swizzled smem via cp.async
__device__ __forceinline__ void load_tile_ca(u32 smdst, const __nv_bfloat16* __restrict__ g,
                                             int rowstride, int tid) {
#pragma unroll
    for (int i = 0; i < 4; i++) {
        int idx = tid + (i << 8);          // 0..1023
        int row = idx >> 3;                // 0..127
        int c8  = (idx & 7) << 3;          // bf16 col 0..56 step 8
        u32 off = (u32)(row * 128 + (c8 << 1));
        cp16(smdst + (off ^ ((off >> 3) & 0x70u)),
             g + (size_t)row * rowstride + c8);
    }
}

// per-lane fragment addressing constants
struct LaneCtx {
    u32 raoff[4];   // A row offsets (per 16-row m tile)
    u32 rboff[2];   // B row offsets (per 16-row n-pair)
    u32 colk[4];    // swizzled column offset per k16
};
__device__ __forceinline__ LaneCtx make_ctx(int tid) {
    LaneCtx cx;
    const int lane = tid & 31;
    const int wm = (tid >> 5) >> 2;        // 0..1
    const int wn = (tid >> 5) & 3;         // 0..3
    const int quad = lane >> 3, r8 = lane & 7;
    const int cb = (quad >> 1) << 4;               // 0 or 16 bytes (k+8 select)
    const int rsel = ((quad & 1) << 3) + r8;       // 0..15
    const u32 xsw = (u32)(r8 << 4);                // SW128 xor (row&7)<<4
#pragma unroll
    for (int mi = 0; mi < 4; mi++) cx.raoff[mi] = (u32)((wm*64 + mi*16 + rsel) * 128);
#pragma unroll
    for (int p = 0; p < 2; p++)    cx.rboff[p]  = (u32)((wn*32 + p*16 + rsel) * 128);
#pragma unroll
    for (int k = 0; k < 4; k++)    cx.colk[k]   = ((u32)(cb + k*32)) ^ xsw;
    return cx;
}

// MMA over one resident 64-wide K chunk (4 k16 steps, 3-way bf16 split)
__device__ __forceinline__ void mma_chunk(float acc[4][4][4], const LaneCtx& cx, u32 stage) {
    const u32 Ab = stage, Bb = stage + 2*TILE_B;
#pragma unroll
    for (int k16 = 0; k16 < 4; k16++) {
        const u32 c = cx.colk[k16];
        u32 ah[4][4], al[4][4], bh[2][4], bl[2][4];
#pragma unroll
        for (int mi = 0; mi < 4; mi++) {
            ldsm4(ah[mi], Ab + cx.raoff[mi] + c);
            ldsm4(al[mi], Ab + TILE_B + cx.raoff[mi] + c);
        }
#pragma unroll
        for (int p = 0; p < 2; p++) {
            ldsm4(bh[p], Bb + cx.rboff[p] + c);
            ldsm4(bl[p], Bb + TILE_B + cx.rboff[p] + c);
        }
#pragma unroll
        for (int mi = 0; mi < 4; mi++)
#pragma unroll
            for (int ni = 0; ni < 4; ni++) {
                const int p = ni >> 1, s = ni & 1;
                hmma(acc[mi][ni], ah[mi], bh[p][s], bh[p][s+2]);
                hmma(acc[mi][ni], ah[mi], bl[p][s], bl[p][s+2]);
                hmma(acc[mi][ni], al[mi], bh[p][s], bh[p][s+2]);
            }
    }
}

// =====================================================================
// GEMM 1: scores. D[n,e] = X·W1^T; epilogue: spart = sum_e tanh(D+b1)*w2
// =====================================================================
__global__ __launch_bounds__(256)
void gemm_score_mma(const float* __restrict__ b1, const float* __restrict__ w2)
{
    extern __shared__ char dyn[];
    __shared__ float red[128][4];
    const int tid = threadIdx.x;
    const int n0 = blockIdx.x * 128;
    const int e0 = blockIdx.y * 128;
    const u32 dynb = smem_u32(dyn);
    const u32 base = (dynb + 1023u) & ~1023u;

    const __nv_bfloat16* Ah = g_Xh  + (size_t)n0 * DD;
    const __nv_bfloat16* Al = g_Xl  + (size_t)n0 * DD;
    const __nv_bfloat16* Bh = g_W1h + (size_t)e0 * DD;
    const __nv_bfloat16* Bl = g_W1l + (size_t)e0 * DD;

    const LaneCtx cx = make_ctx(tid);
    float acc[4][4][4];
#pragma unroll
    for (int i = 0; i < 4; i++)
#pragma unroll
        for (int j = 0; j < 4; j++)
#pragma unroll
            for (int q = 0; q < 4; q++) acc[i][j][q] = 0.f;

    // prologue: chunk 0 -> stage 0
    load_tile_ca(base,            Ah, DD, tid);
    load_tile_ca(base + TILE_B,   Al, DD, tid);
    load_tile_ca(base + 2*TILE_B, Bh, DD, tid);
    load_tile_ca(base + 3*TILE_B, Bl, DD, tid);
    CP_COMMIT();

    const int NCH = DD / 64;   // 16
    for (int kt = 0; kt < NCH; kt++) {
        if (kt > 0) __syncthreads();   // stage being filled was read 2 iters ago
        if (kt + 1 < NCH) {
            const u32 sb2 = base + ((u32)((kt+1) & 1)) * STAGE_B;
            const int ko = (kt + 1) * 64;
            load_tile_ca(sb2,            Ah + ko, DD, tid);
            load_tile_ca(sb2 + TILE_B,   Al + ko, DD, tid);
            load_tile_ca(sb2 + 2*TILE_B, Bh + ko, DD, tid);
            load_tile_ca(sb2 + 3*TILE_B, Bl + ko, DD, tid);
            CP_COMMIT();
            CP_WAIT1();
        } else {
            CP_WAIT0();
        }
        __syncthreads();
        mma_chunk(acc, cx, base + ((u32)(kt & 1)) * STAGE_B);
    }

    // epilogue
    const int lane = tid & 31;
    const int wm = (tid >> 5) >> 2, wn = (tid >> 5) & 3;
    float b1x[4], b1y[4], w2x[4], w2y[4];
#pragma unroll
    for (int ni = 0; ni < 4; ni++) {
        const int col = e0 + wn*32 + ni*8 + 2*(lane & 3);
        float2 bv = *(const float2*)(b1 + col);
        float2 wv = *(const float2*)(w2 + col);
        b1x[ni] = bv.x; b1y[ni] = bv.y; w2x[ni] = wv.x; w2y[ni] = wv.y;
    }
#pragma unroll
    for (int mi = 0; mi < 4; mi++)
#pragma unroll
        for (int h2 = 0; h2 < 2; h2++) {
            float s = 0.f;
#pragma unroll
            for (int ni = 0; ni < 4; ni++) {
                s += tanh_acc(acc[mi][ni][h2*2+0] + b1x[ni]) * w2x[ni];
                s += tanh_acc(acc[mi][ni][h2*2+1] + b1y[ni]) * w2y[ni];
            }
            s += __shfl_xor_sync(0xffffffffu, s, 1);
            s += __shfl_xor_sync(0xffffffffu, s, 2);
            if ((lane & 3) == 0)
                red[wm*64 + mi*16 + h2*8 + (lane >> 2)][wn] = s;
        }
    __syncthreads();
    if (tid < 128)
        g_spart[(size_t)blockIdx.y * NTOK + n0 + tid] =
            red[tid][0] + red[tid][1] + red[tid][2] + red[tid][3];
}

// =====================================================================
// Kernel 2: per-batch max + e = exp(s + b2 - m)
// =====================================================================
__global__ void softmax_prep(const float* __restrict__ b2)
{
    const int b = blockIdx.x, tid = threadIdx.x;   // 256 threads
    float vloc[16];
    float mx = -INFINITY;
    const float b2v = b2[0];
#pragma unroll
    for (int i = 0; i < 16; i++) {
        int t = tid + i * 256;
        float s = 0.f;
#pragma unroll
        for (int eb = 0; eb < 8; eb++) s += g_spart[(size_t)eb * NTOK + b * TT + t];
        s += b2v;
        vloc[i] = s;
        mx = fmaxf(mx, s);
    }
    __shared__ float sm[256];
    sm[tid] = mx; __syncthreads();
    for (int off = 128; off > 0; off >>= 1) {
        if (tid < off) sm[tid] = fmaxf(sm[tid], sm[tid + off]);
        __syncthreads();
    }
    float m = sm[0];
#pragma unroll
    for (int i = 0; i < 16; i++) {
        int t = tid + i * 256;
        g_e[b * TT + t] = expf(vloc[i] - m);
    }
}

// =====================================================================
// Kernel 3: causal prefix scan; emits ctx as bf16 hi/lo directly.
// =====================================================================
__global__ void scan_kernel(const float* __restrict__ X)
{
    const int b = blockIdx.y;
    const int d = blockIdx.x * 128 + threadIdx.x;
    const float* xb = X + (size_t)b * TT * DD + d;
    __nv_bfloat16* chp = g_Ch + (size_t)b * TT * DD + d;
    __nv_bfloat16* clp = g_Cl + (size_t)b * TT * DD + d;

    __shared__ float es[128];
    float num = 0.f, den = 0.f;

    for (int tc = 0; tc < TT; tc += 128) {
        __syncthreads();
        es[threadIdx.x] = g_e[b * TT + tc + threadIdx.x];
        __syncthreads();
#pragma unroll 8
        for (int tt = 0; tt < 128; ++tt) {
            float ev = es[tt];
            den += ev;
            num = fmaf(ev, xb[(size_t)(tc + tt) * DD], num);
            float rcp;
            asm("rcp.approx.f32 %0, %1;" : "=f"(rcp) : "f"(den));
            float ctxv = num * rcp;
            __nv_bfloat16 h = __float2bfloat16(ctxv);
            size_t off = (size_t)(tc + tt) * DD;
            chp[off] = h;
            clp[off] = __float2bfloat16(ctxv - __bfloat162float(h));
        }
    }
}

// =====================================================================
// GEMM 2: out = tanh([ctx,x]·Wc^T + bc); K split ctx(0:1024)/x(1024:2048)
// =====================================================================
__global__ __launch_bounds__(256)
void gemm_out_mma(const float* __restrict__ bc, float* __restrict__ out)
{
    extern __shared__ char dyn[];
    const int tid = threadIdx.x;
    const int n0 = blockIdx.x * 128;
    const int d0 = blockIdx.y * 128;
    const u32 dynb = smem_u32(dyn);
    const u32 base = (dynb + 1023u) & ~1023u;

    const __nv_bfloat16* Bh = g_Wch + (size_t)d0 * K2;
    const __nv_bfloat16* Bl = g_Wcl + (size_t)d0 * K2;

    const LaneCtx cx = make_ctx(tid);
    float acc[4][4][4];
#pragma unroll
    for (int i = 0; i < 4; i++)
#pragma unroll
        for (int j = 0; j < 4; j++)
#pragma unroll
            for (int q = 0; q < 4; q++) acc[i][j][q] = 0.f;

    // A source for K offset ko
    auto getA = [&](int ko, const __nv_bfloat16*& ah, const __nv_bfloat16*& al) {
        if (ko < DD) { ah = g_Ch + (size_t)n0 * DD + ko; al = g_Cl + (size_t)n0 * DD + ko; }
        else         { ah = g_Xh + (size_t)n0 * DD + (ko - DD); al = g_Xl + (size_t)n0 * DD + (ko - DD); }
    };

    {   // prologue: chunk 0 -> stage 0
        const __nv_bfloat16 *ah, *al; getA(0, ah, al);
        load_tile_ca(base,            ah, DD, tid);
        load_tile_ca(base + TILE_B,   al, DD, tid);
        load_tile_ca(base + 2*TILE_B, Bh, K2, tid);
        load_tile_ca(base + 3*TILE_B, Bl, K2, tid);
        CP_COMMIT();
    }

    const int NCH = K2 / 64;   // 32
    for (int kt = 0; kt < NCH; kt++) {
        if (kt > 0) __syncthreads();
        if (kt + 1 < NCH) {
            const u32 sb2 = base + ((u32)((kt+1) & 1)) * STAGE_B;
            const int ko = (kt + 1) * 64;
            const __nv_bfloat16 *ah, *al; getA(ko, ah, al);
            load_tile_ca(sb2,            ah, DD, tid);
            load_tile_ca(sb2 + TILE_B,   al, DD, tid);
            load_tile_ca(sb2 + 2*TILE_B, Bh + ko, K2, tid);
            load_tile_ca(sb2 + 3*TILE_B, Bl + ko, K2, tid);
            CP_COMMIT();
            CP_WAIT1();
        } else {
            CP_WAIT0();
        }
        __syncthreads();
        mma_chunk(acc, cx, base + ((u32)(kt & 1)) * STAGE_B);
    }

    // epilogue: tanh(acc + bc) -> out, float2 stores
    const int lane = tid & 31;
    const int wm = (tid >> 5) >> 2, wn = (tid >> 5) & 3;
#pragma unroll
    for (int ni = 0; ni < 4; ni++) {
        const int colb = d0 + wn*32 + ni*8 + 2*(lane & 3);
        const float2 bcv = *(const float2*)(bc + colb);
#pragma unroll
        for (int mi = 0; mi < 4; mi++) {
            const int row0 = n0 + wm*64 + mi*16 + (lane >> 2);
            float2 o0, o1;
            o0.x = tanh_acc(acc[mi][ni][0] + bcv.x);
            o0.y = tanh_acc(acc[mi][ni][1] + bcv.y);
            o1.x = tanh_acc(acc[mi][ni][2] + bcv.x);
            o1.y = tanh_acc(acc[mi][ni][3] + bcv.y);
            *(float2*)(out + (size_t)row0 * DD + colb) = o0;
            *(float2*)(out + (size_t)(row0 + 8) * DD + colb) = o1;
        }
    }
}

// =====================================================================
// converters: fp32 -> bf16 hi/lo (write device globals directly)
// =====================================================================
struct __align__(8) bf4 { __nv_bfloat16 v[4]; };

__device__ __forceinline__ void split4(const float* __restrict__ src,
                                       __nv_bfloat16* __restrict__ hi,
                                       __nv_bfloat16* __restrict__ lo, int i) {
    float4 v = ((const float4*)src)[i];
    bf4 h, l;
    float f[4] = {v.x, v.y, v.z, v.w};
#pragma unroll
    for (int j = 0; j < 4; j++) {
        __nv_bfloat16 hb = __float2bfloat16(f[j]);
        h.v[j] = hb;
        l.v[j] = __float2bfloat16(f[j] - __bfloat162float(hb));
    }
    ((bf4*)hi)[i] = h;
    ((bf4*)lo)[i] = l;
}
__global__ void cvt_x(const float* __restrict__ src) {
    int i = blockIdx.x * blockDim.x + threadIdx.x;
    if (i < NTOK * (DD/4)) split4(src, g_Xh, g_Xl, i);
}
__global__ void cvt_w1(const float* __restrict__ src) {
    int i = blockIdx.x * blockDim.x + threadIdx.x;
    if (i < DD * (DD/4)) split4(src, g_W1h, g_W1l, i);
}
__global__ void cvt_wc(const float* __restrict__ src) {
    int i = blockIdx.x * blockDim.x + threadIdx.x;
    if (i < DD * (K2/4)) split4(src, g_Wch, g_Wcl, i);
}

// =====================================================================
extern "C" void kernel_launch(void* const* d_in, const int* in_sizes, int n_in,
                              void* d_out, int out_size)
{
    const float* x  = (const float*)d_in[0];
    const float* W1 = (const float*)d_in[1];
    const float* b1 = (const float*)d_in[2];
    const float* w2 = (const float*)d_in[3];
    const float* b2 = (const float*)d_in[4];
    const float* Wc = (const float*)d_in[5];
    const float* bc = (const float*)d_in[6];
    float* out = (float*)d_out;

    cudaFuncSetAttribute(gemm_score_mma, cudaFuncAttributeMaxDynamicSharedMemorySize, DYN_B);
    cudaFuncSetAttribute(gemm_out_mma,   cudaFuncAttributeMaxDynamicSharedMemorySize, DYN_B);

    cvt_x <<<(NTOK*(DD/4) + 255)/256, 256>>>(x);
    cvt_w1<<<(DD*(DD/4)   + 255)/256, 256>>>(W1);
    cvt_wc<<<(DD*(K2/4)   + 255)/256, 256>>>(Wc);

    dim3 g1(NTOK / 128, DD / 128);      // 256 x 8
    gemm_score_mma<<<g1, 256, DYN_B>>>(b1, w2);

    softmax_prep<<<BB, 256>>>(b2);

    dim3 g3(DD / 128, BB);              // 8 x 8
    scan_kernel<<<g3, 128>>>(x);

    dim3 g4(NTOK / 128, DD / 128);      // 256 x 8
    gemm_out_mma<<<g4, 256, DYN_B>>>(bc, out);
}

// round 7
// speedup vs baseline: 1.9276x; 1.0473x over previous
#include <cuda_runtime.h>
#include <cuda_bf16.h>
#include <math.h>

// Problem constants
#define BB   8
#define TT   4096
#define DD   1024
#define NTOK (BB*TT)          // 32768
#define K2   (2*DD)           // 2048

using u32 = unsigned int;
using u64 = unsigned long long;

// ---------------- scratch (static device globals: allowed) ----------------
__device__ float g_spart[8 * NTOK];
__device__ float g_e[NTOK];
__device__ __nv_bfloat16 g_Xh[(size_t)NTOK * DD];
__device__ __nv_bfloat16 g_Xl[(size_t)NTOK * DD];
__device__ __nv_bfloat16 g_Ch[(size_t)NTOK * DD];
__device__ __nv_bfloat16 g_Cl[(size_t)NTOK * DD];
__device__ __nv_bfloat16 g_W1h[(size_t)DD * DD];
__device__ __nv_bfloat16 g_W1l[(size_t)DD * DD];
__device__ __nv_bfloat16 g_Wch[(size_t)DD * K2];
__device__ __nv_bfloat16 g_Wcl[(size_t)DD * K2];

// ---------------- helpers ----------------
__device__ __forceinline__ u32 smem_u32(const void* p) {
    u32 a;
    asm("{ .reg .u64 t; cvta.to.shared.u64 t, %1; cvt.u32.u64 %0, t; }" : "=r"(a) : "l"(p));
    return a;
}
__device__ __forceinline__ void cp16(u32 dst, const void* src) {
    asm volatile("cp.async.cg.shared.global [%0], [%1], 16;" :: "r"(dst), "l"(src));
}
#define CP_COMMIT() asm volatile("cp.async.commit_group;" ::: "memory")
#define CP_WAIT1()  asm volatile("cp.async.wait_group 1;" ::: "memory")
#define CP_WAIT0()  asm volatile("cp.async.wait_group 0;" ::: "memory")

__device__ __forceinline__ void ldsm4(u32* r, u32 addr) {
    asm volatile("ldmatrix.sync.aligned.m8n8.x4.shared.b16 {%0,%1,%2,%3}, [%4];"
                 : "=r"(r[0]), "=r"(r[1]), "=r"(r[2]), "=r"(r[3]) : "r"(addr));
}
__device__ __forceinline__ void hmma(float* c, const u32* a, u32 b0, u32 b1) {
    asm volatile("mma.sync.aligned.m16n8k16.row.col.f32.bf16.bf16.f32 "
                 "{%0,%1,%2,%3}, {%4,%5,%6,%7}, {%8,%9}, {%0,%1,%2,%3};"
                 : "+f"(c[0]), "+f"(c[1]), "+f"(c[2]), "+f"(c[3])
                 : "r"(a[0]), "r"(a[1]), "r"(a[2]), "r"(a[3]), "r"(b0), "r"(b1));
}
// accurate fast tanh: 1 - 2/(1+e^{2x})
__device__ __forceinline__ float tanh_acc(float x) {
    float e, r;
    asm("ex2.approx.f32 %0, %1;" : "=f"(e) : "f"(x * 2.885390081777927f));
    asm("rcp.approx.f32 %0, %1;" : "=f"(r) : "f"(e + 1.0f));
    return fmaf(-2.0f, r, 1.0f);
}

// ---------------- tile geometry ----------------
// CTA tile 256(M) x 128(N), K-chunk 64. 16 warps (4x4), warp tile 64x32.
#define A_TILE   32768                 // 256 x 64 bf16
#define B_TILE   16384                 // 128 x 64 bf16
#define STAGE_B  (2*A_TILE + 2*B_TILE) // 96 KB (Ahi,Alo,Bhi,Blo)
#define DYN_B    (2*STAGE_B + 1024)

// load 256x64-bf16 tile into SW128-swizzled smem (512 threads)
__device__ __forceinline__ void load_A64(u32 smdst, const __nv_bfloat16* __restrict__ g,
                                         int rowstride, int tid) {
#pragma unroll
    for (int i = 0; i < 4; i++) {
        int idx = tid + (i << 9);
        int row = idx >> 3;
        int c8  = (idx & 7) << 3;
        u32 off = (u32)(row * 128 + (c8 << 1));
        cp16(smdst + (off ^ ((off >> 3) & 0x70u)), g + (size_t)row * rowstride + c8);
    }
}
// load 128x64-bf16 tile (512 threads)
__device__ __forceinline__ void load_B64(u32 smdst, const __nv_bfloat16* __restrict__ g,
                                         int rowstride, int tid) {
#pragma unroll
    for (int i = 0; i < 2; i++) {
        int idx = tid + (i << 9);
        int row = idx >> 3;
        int c8  = (idx & 7) << 3;
        u32 off = (u32)(row * 128 + (c8 << 1));
        cp16(smdst + (off ^ ((off >> 3) & 0x70u)), g + (size_t)row * rowstride + c8);
    }
}

// per-lane fragment addressing constants
struct LaneCtx {
    u32 raoff[4];   // A row offsets per 16-row m tile
    u32 rboff[2];   // B row offsets per 16-row n-pair
    u32 colk[4];    // swizzled column offset per k16
};
__device__ __forceinline__ LaneCtx make_ctx(int tid) {
    LaneCtx cx;
    const int lane = tid & 31;
    const int wm = (tid >> 5) >> 2;        // 0..3
    const int wn = (tid >> 5) & 3;         // 0..3
    const int quad = lane >> 3, r8 = lane & 7;
    const int cb = (quad >> 1) << 4;
    const int rsel = ((quad & 1) << 3) + r8;
    const u32 xsw = (u32)(r8 << 4);
#pragma unroll
    for (int mi = 0; mi < 4; mi++) cx.raoff[mi] = (u32)((wm*64 + mi*16 + rsel) * 128);
#pragma unroll
    for (int p = 0; p < 2; p++)    cx.rboff[p]  = (u32)((wn*32 + p*16 + rsel) * 128);
#pragma unroll
    for (int k = 0; k < 4; k++)    cx.colk[k]   = ((u32)(cb + k*32)) ^ xsw;
    return cx;
}

// MMA over one resident 64-wide K chunk (register-pressure-safe ordering)
__device__ __forceinline__ void mma_chunk(float acc[4][4][4], const LaneCtx& cx, u32 stage) {
    const u32 Ahb = stage, Alb = stage + A_TILE;
    const u32 Bhb = stage + 2*A_TILE, Blb = stage + 2*A_TILE + B_TILE;
#pragma unroll
    for (int k16 = 0; k16 < 4; k16++) {
        const u32 c = cx.colk[k16];
        u32 bh[2][4], bl[2][4];
#pragma unroll
        for (int p = 0; p < 2; p++) {
            ldsm4(bh[p], Bhb + cx.rboff[p] + c);
            ldsm4(bl[p], Blb + cx.rboff[p] + c);
        }
#pragma unroll
        for (int mi = 0; mi < 4; mi++) {
            u32 ah[4], al[4];
            ldsm4(ah, Ahb + cx.raoff[mi] + c);
            ldsm4(al, Alb + cx.raoff[mi] + c);
#pragma unroll
            for (int ni = 0; ni < 4; ni++) {
                const int p = ni >> 1, s = ni & 1;
                hmma(acc[mi][ni], ah, bh[p][s], bh[p][s+2]);
                hmma(acc[mi][ni], ah, bl[p][s], bl[p][s+2]);
                hmma(acc[mi][ni], al, bh[p][s], bh[p][s+2]);
            }
        }
    }
}

// =====================================================================
// GEMM 1: scores. D[n,e] = X·W1^T; epilogue: spart = sum_e tanh(D+b1)*w2
// grid = (e-tiles=8, n-tiles=128); consecutive blocks share the A tile.
// =====================================================================
__global__ __launch_bounds__(512)
void gemm_score_mma(const float* __restrict__ b1, const float* __restrict__ w2)
{
    extern __shared__ char dyn[];
    __shared__ float red[256][4];
    const int tid = threadIdx.x;
    const int e0 = blockIdx.x * 128;
    const int n0 = blockIdx.y * 256;
    const u32 dynb = smem_u32(dyn);
    const u32 base = (dynb + 1023u) & ~1023u;

    const __nv_bfloat16* Ah = g_Xh  + (size_t)n0 * DD;
    const __nv_bfloat16* Al = g_Xl  + (size_t)n0 * DD;
    const __nv_bfloat16* Bh = g_W1h + (size_t)e0 * DD;
    const __nv_bfloat16* Bl = g_W1l + (size_t)e0 * DD;

    const LaneCtx cx = make_ctx(tid);
    float acc[4][4][4];
#pragma unroll
    for (int i = 0; i < 4; i++)
#pragma unroll
        for (int j = 0; j < 4; j++)
#pragma unroll
            for (int q = 0; q < 4; q++) acc[i][j][q] = 0.f;

    load_A64(base,            Ah, DD, tid);
    load_A64(base + A_TILE,   Al, DD, tid);
    load_B64(base + 2*A_TILE,          Bh, DD, tid);
    load_B64(base + 2*A_TILE + B_TILE, Bl, DD, tid);
    CP_COMMIT();

    const int NCH = DD / 64;   // 16
    for (int kt = 0; kt < NCH; kt++) {
        if (kt > 0) __syncthreads();
        if (kt + 1 < NCH) {
            const u32 sb2 = base + ((u32)((kt+1) & 1)) * STAGE_B;
            const int ko = (kt + 1) * 64;
            load_A64(sb2,            Ah + ko, DD, tid);
            load_A64(sb2 + A_TILE,   Al + ko, DD, tid);
            load_B64(sb2 + 2*A_TILE,          Bh + ko, DD, tid);
            load_B64(sb2 + 2*A_TILE + B_TILE, Bl + ko, DD, tid);
            CP_COMMIT();
            CP_WAIT1();
        } else {
            CP_WAIT0();
        }
        __syncthreads();
        mma_chunk(acc, cx, base + ((u32)(kt & 1)) * STAGE_B);
    }

    // epilogue: tanh(D+b1)*w2, reduce over 128 e-cols
    const int lane = tid & 31;
    const int wm = (tid >> 5) >> 2, wn = (tid >> 5) & 3;
    float b1x[4], b1y[4], w2x[4], w2y[4];
#pragma unroll
    for (int ni = 0; ni < 4; ni++) {
        const int col = e0 + wn*32 + ni*8 + 2*(lane & 3);
        float2 bv = *(const float2*)(b1 + col);
        float2 wv = *(const float2*)(w2 + col);
        b1x[ni] = bv.x; b1y[ni] = bv.y; w2x[ni] = wv.x; w2y[ni] = wv.y;
    }
#pragma unroll
    for (int mi = 0; mi < 4; mi++)
#pragma unroll
        for (int h2 = 0; h2 < 2; h2++) {
            float s = 0.f;
#pragma unroll
            for (int ni = 0; ni < 4; ni++) {
                s += tanh_acc(acc[mi][ni][h2*2+0] + b1x[ni]) * w2x[ni];
                s += tanh_acc(acc[mi][ni][h2*2+1] + b1y[ni]) * w2y[ni];
            }
            s += __shfl_xor_sync(0xffffffffu, s, 1);
            s += __shfl_xor_sync(0xffffffffu, s, 2);
            if ((lane & 3) == 0)
                red[wm*64 + mi*16 + h2*8 + (lane >> 2)][wn] = s;
        }
    __syncthreads();
    if (tid < 256)
        g_spart[(size_t)blockIdx.x * NTOK + n0 + tid] =
            red[tid][0] + red[tid][1] + red[tid][2] + red[tid][3];
}

// =====================================================================
// Kernel 2: per-batch max + e = exp(s + b2 - m)
// =====================================================================
__global__ void softmax_prep(const float* __restrict__ b2)
{
    const int b = blockIdx.x, tid = threadIdx.x;   // 256 threads
    float vloc[16];
    float mx = -INFINITY;
    const float b2v = b2[0];
#pragma unroll
    for (int i = 0; i < 16; i++) {
        int t = tid + i * 256;
        float s = 0.f;
#pragma unroll
        for (int eb = 0; eb < 8; eb++) s += g_spart[(size_t)eb * NTOK + b * TT + t];
        s += b2v;
        vloc[i] = s;
        mx = fmaxf(mx, s);
    }
    __shared__ float sm[256];
    sm[tid] = mx; __syncthreads();
    for (int off = 128; off > 0; off >>= 1) {
        if (tid < off) sm[tid] = fmaxf(sm[tid], sm[tid + off]);
        __syncthreads();
    }
    float m = sm[0];
#pragma unroll
    for (int i = 0; i < 16; i++) {
        int t = tid + i * 256;
        g_e[b * TT + t] = expf(vloc[i] - m);
    }
}

// =====================================================================
// Kernel 3: causal prefix scan; emits ctx as bf16 hi/lo directly.
// =====================================================================
__global__ void scan_kernel(const float* __restrict__ X)
{
    const int b = blockIdx.y;
    const int d = blockIdx.x * 128 + threadIdx.x;
    const float* xb = X + (size_t)b * TT * DD + d;
    __nv_bfloat16* chp = g_Ch + (size_t)b * TT * DD + d;
    __nv_bfloat16* clp = g_Cl + (size_t)b * TT * DD + d;

    __shared__ float es[128];
    float num = 0.f, den = 0.f;

    for (int tc = 0; tc < TT; tc += 128) {
        __syncthreads();
        es[threadIdx.x] = g_e[b * TT + tc + threadIdx.x];
        __syncthreads();
#pragma unroll 8
        for (int tt = 0; tt < 128; ++tt) {
            float ev = es[tt];
            den += ev;
            num = fmaf(ev, xb[(size_t)(tc + tt) * DD], num);
            float rcp;
            asm("rcp.approx.f32 %0, %1;" : "=f"(rcp) : "f"(den));
            float ctxv = num * rcp;
            __nv_bfloat16 h = __float2bfloat16(ctxv);
            size_t off = (size_t)(tc + tt) * DD;
            chp[off] = h;
            clp[off] = __float2bfloat16(ctxv - __bfloat162float(h));
        }
    }
}

// =====================================================================
// GEMM 2: out = tanh([ctx,x]·Wc^T + bc); K split ctx(0:1024)/x(1024:2048)
// grid = (d-tiles=8, n-tiles=128)
// =====================================================================
__global__ __launch_bounds__(512)
void gemm_out_mma(const float* __restrict__ bc, float* __restrict__ out)
{
    extern __shared__ char dyn[];
    const int tid = threadIdx.x;
    const int d0 = blockIdx.x * 128;
    const int n0 = blockIdx.y * 256;
    const u32 dynb = smem_u32(dyn);
    const u32 base = (dynb + 1023u) & ~1023u;

    const __nv_bfloat16* Bh = g_Wch + (size_t)d0 * K2;
    const __nv_bfloat16* Bl = g_Wcl + (size_t)d0 * K2;

    const LaneCtx cx = make_ctx(tid);
    float acc[4][4][4];
#pragma unroll
    for (int i = 0; i < 4; i++)
#pragma unroll
        for (int j = 0; j < 4; j++)
#pragma unroll
            for (int q = 0; q < 4; q++) acc[i][j][q] = 0.f;

    auto getA = [&](int ko, const __nv_bfloat16*& ah, const __nv_bfloat16*& al) {
        if (ko < DD) { ah = g_Ch + (size_t)n0 * DD + ko; al = g_Cl + (size_t)n0 * DD + ko; }
        else         { ah = g_Xh + (size_t)n0 * DD + (ko - DD); al = g_Xl + (size_t)n0 * DD + (ko - DD); }
    };

    {
        const __nv_bfloat16 *ah, *al; getA(0, ah, al);
        load_A64(base,            ah, DD, tid);
        load_A64(base + A_TILE,   al, DD, tid);
        load_B64(base + 2*A_TILE,          Bh, K2, tid);
        load_B64(base + 2*A_TILE + B_TILE, Bl, K2, tid);
        CP_COMMIT();
    }

    const int NCH = K2 / 64;   // 32
    for (int kt = 0; kt < NCH; kt++) {
        if (kt > 0) __syncthreads();
        if (kt + 1 < NCH) {
            const u32 sb2 = base + ((u32)((kt+1) & 1)) * STAGE_B;
            const int ko = (kt + 1) * 64;
            const __nv_bfloat16 *ah, *al; getA(ko, ah, al);
            load_A64(sb2,            ah, DD, tid);
            load_A64(sb2 + A_TILE,   al, DD, tid);
            load_B64(sb2 + 2*A_TILE,          Bh + ko, K2, tid);
            load_B64(sb2 + 2*A_TILE + B_TILE, Bl + ko, K2, tid);
            CP_COMMIT();
            CP_WAIT1();
        } else {
            CP_WAIT0();
        }
        __syncthreads();
        mma_chunk(acc, cx, base + ((u32)(kt & 1)) * STAGE_B);
    }

    // epilogue: tanh(acc + bc) -> out
    const int lane = tid & 31;
    const int wm = (tid >> 5) >> 2, wn = (tid >> 5) & 3;
#pragma unroll
    for (int ni = 0; ni < 4; ni++) {
        const int colb = d0 + wn*32 + ni*8 + 2*(lane & 3);
        const float2 bcv = *(const float2*)(bc + colb);
#pragma unroll
        for (int mi = 0; mi < 4; mi++) {
            const int row0 = n0 + wm*64 + mi*16 + (lane >> 2);
            float2 o0, o1;
            o0.x = tanh_acc(acc[mi][ni][0] + bcv.x);
            o0.y = tanh_acc(acc[mi][ni][1] + bcv.y);
            o1.x = tanh_acc(acc[mi][ni][2] + bcv.x);
            o1.y = tanh_acc(acc[mi][ni][3] + bcv.y);
            *(float2*)(out + (size_t)row0 * DD + colb) = o0;
            *(float2*)(out + (size_t)(row0 + 8) * DD + colb) = o1;
        }
    }
}

// =====================================================================
// converters: fp32 -> bf16 hi/lo
// =====================================================================
struct __align__(8) bf4 { __nv_bfloat16 v[4]; };

__device__ __forceinline__ void split4(const float* __restrict__ src,
                                       __nv_bfloat16* __restrict__ hi,
                                       __nv_bfloat16* __restrict__ lo, int i) {
    float4 v = ((const float4*)src)[i];
    bf4 h, l;
    float f[4] = {v.x, v.y, v.z, v.w};
#pragma unroll
    for (int j = 0; j < 4; j++) {
        __nv_bfloat16 hb = __float2bfloat16(f[j]);
        h.v[j] = hb;
        l.v[j] = __float2bfloat16(f[j] - __bfloat162float(hb));
    }
    ((bf4*)hi)[i] = h;
    ((bf4*)lo)[i] = l;
}
__global__ void cvt_x(const float* __restrict__ src) {
    int i = blockIdx.x * blockDim.x + threadIdx.x;
    if (i < NTOK * (DD/4)) split4(src, g_Xh, g_Xl, i);
}
__global__ void cvt_w1(const float* __restrict__ src) {
    int i = blockIdx.x * blockDim.x + threadIdx.x;
    if (i < DD * (DD/4)) split4(src, g_W1h, g_W1l, i);
}
__global__ void cvt_wc(const float* __restrict__ src) {
    int i = blockIdx.x * blockDim.x + threadIdx.x;
    if (i < DD * (K2/4)) split4(src, g_Wch, g_Wcl, i);
}

// =====================================================================
extern "C" void kernel_launch(void* const* d_in, const int* in_sizes, int n_in,
                              void* d_out, int out_size)
{
    const float* x  = (const float*)d_in[0];
    const float* W1 = (const float*)d_in[1];
    const float* b1 = (const float*)d_in[2];
    const float* w2 = (const float*)d_in[3];
    const float* b2 = (const float*)d_in[4];
    const float* Wc = (const float*)d_in[5];
    const float* bc = (const float*)d_in[6];
    float* out = (float*)d_out;

    cudaFuncSetAttribute(gemm_score_mma, cudaFuncAttributeMaxDynamicSharedMemorySize, DYN_B);
    cudaFuncSetAttribute(gemm_out_mma,   cudaFuncAttributeMaxDynamicSharedMemorySize, DYN_B);

    cvt_x <<<(NTOK*(DD/4) + 255)/256, 256>>>(x);
    cvt_w1<<<(DD*(DD/4)   + 255)/256, 256>>>(W1);
    cvt_wc<<<(DD*(K2/4)   + 255)/256, 256>>>(Wc);

    dim3 g1(DD / 128, NTOK / 256);      // (8, 128): e-tiles fast, share A
    gemm_score_mma<<<g1, 512, DYN_B>>>(b1, w2);

    softmax_prep<<<BB, 256>>>(b2);

    dim3 g3(DD / 128, BB);              // 8 x 8
    scan_kernel<<<g3, 128>>>(x);

    dim3 g4(DD / 128, NTOK / 256);      // (8, 128): d-tiles fast
    gemm_out_mma<<<g4, 512, DYN_B>>>(bc, out);
}